// round 4
// baseline (speedup 1.0000x reference)
#include <cuda_runtime.h>
#include <cuda_fp16.h>
#include <cstdint>

#define DEV_INLINE __device__ __forceinline__

// Problem constants (fixed by setup_inputs)
constexpr int BB   = 32;
constexpr int T    = 256;
constexpr int E    = 512;
constexpr int HD   = 1024;
constexpr int HE   = 512;
constexpr int NSEQ = BB * T;                        // 8192
constexpr int OUT_OFF_H = BB * T * HD;              // 8388608
constexpr int OUT_OFF_C = OUT_OFF_H + 2 * BB * HD;  // +65536

// ---------------- static device scratch ----------------
// frag-ready state buffers: uint2 j = k016*128 + q*32 + col ; halves j*4 + hs*2 + par
__device__ uint2 g_h0F[2][8192];          // decoder layer0 h, double buffered (K=1024)
__device__ uint2 g_h1F[2][8192];          // decoder layer1 h
__device__ uint2 g_ehF[2][2][4096];       // encoder h [dir][parity] (K=512)
// frag-ready sequences: uint2 j = k016*32768 + q*8192 + n
__device__ uint2 g_X2F[2097152];          // decoder outputs (16MB)
__device__ uint2 g_Y0F[2097152];          // encoder layer0 outputs
__device__ float g_Z[(size_t)2 * 2048 * NSEQ];  // input projections per dir (134MB)
__device__ float g_gconst[4096];          // x0 @ Wih0^T + bih0 + bhh0
__device__ float g_bsum1[4096];           // bih1 + bhh1
__device__ float g_encb[8192];            // enc bih+bhh per (layer,dir)

__device__ unsigned g_bar_cnt;
__device__ volatile unsigned g_bar_gen;

// ---------------- helpers ----------------
DEV_INLINE float sigf(float x) { return 1.0f / (1.0f + expf(-x)); }

DEV_INLINE void grid_barrier() {
    __syncthreads();
    if (threadIdx.x == 0) {
        unsigned nb = gridDim.x;
        unsigned gen = g_bar_gen;
        __threadfence();
        if (atomicAdd(&g_bar_cnt, 1u) == nb - 1u) {
            atomicExch(&g_bar_cnt, 0u);
            __threadfence();
            g_bar_gen = gen + 1u;
        } else {
            while (g_bar_gen == gen) { }
        }
        __threadfence();   // gpu-scope fence -> CCTL.IVALL: fresh L1 view of h states
    }
    __syncthreads();
}

DEV_INLINE void mma_16816(float* c, uint32_t a0, uint32_t a1, uint32_t a2, uint32_t a3,
                          uint32_t b0, uint32_t b1) {
    asm volatile(
        "mma.sync.aligned.m16n8k16.row.col.f32.f16.f16.f32 "
        "{%0,%1,%2,%3}, {%4,%5,%6,%7}, {%8,%9}, {%0,%1,%2,%3};\n"
        : "+f"(c[0]), "+f"(c[1]), "+f"(c[2]), "+f"(c[3])
        : "r"(a0), "r"(a1), "r"(a2), "r"(a3), "r"(b0), "r"(b1));
}

// m16n8 tile GEMM: A from smem (row-major, fp16, padded pitch), B frag-ready uint2.
DEV_INLINE void gemm_fr(const __half* __restrict__ As, int pitch, int K16,
                        const uint2* __restrict__ Bf, int nstr, int mt, int colbase,
                        int lane, float acc[4]) {
    const int g = lane >> 2, q = lane & 3;
    const __half* r0 = As + (size_t)(mt * 16 + g) * pitch;
    const __half* r1 = r0 + 8 * pitch;
    const uint2* bp = Bf + (size_t)q * nstr + colbase + g;
#pragma unroll 8
    for (int k = 0; k < K16; k++) {
        uint32_t a0 = *(const uint32_t*)(r0 + k * 16 + 2 * q);
        uint32_t a1 = *(const uint32_t*)(r1 + k * 16 + 2 * q);
        uint32_t a2 = *(const uint32_t*)(r0 + k * 16 + 8 + 2 * q);
        uint32_t a3 = *(const uint32_t*)(r1 + k * 16 + 8 + 2 * q);
        uint2 bv = bp[(size_t)k * 4 * nstr];
        mma_16816(acc, a0, a1, a2, a3, bv.x, bv.y);
    }
}

DEV_INLINE void frag_st(float* gsm, int mt, int colbase, int lane, const float acc[4]) {
    const int g = lane >> 2, q = lane & 3;
    float* p = gsm + (mt * 16 + g) * 33 + colbase + 2 * q;
    p[0] = acc[0]; p[1] = acc[1];
    p[8 * 33] = acc[2]; p[8 * 33 + 1] = acc[3];
}

// state-buffer half index for feature f, batch b
DEV_INLINE int st_hidx(int f, int b) {
    int kr = f >> 1;
    return (kr >> 3) * 512 + (kr & 3) * 128 + b * 4 + (((kr >> 2) & 1) << 1) + (f & 1);
}
// sequence-buffer half base for feature f (add n*4)
DEV_INLINE int seq_base(int f) {
    int kr = f >> 1;
    return (kr >> 3) * 131072 + (kr & 3) * 32768 + (((kr >> 2) & 1) << 1) + (f & 1);
}

// ---------------- small setup kernels ----------------
__global__ void k_gconst(const float* __restrict__ emb, const float* __restrict__ Wih0,
                         const float* __restrict__ bih0, const float* __restrict__ bhh0) {
    int j = blockIdx.x * blockDim.x + threadIdx.x;
    if (j >= 4096) return;
    const float4* xr = (const float4*)(emb + E);               // BOS row
    const float4* wr = (const float4*)(Wih0 + (size_t)j * E);
    float s = 0.f;
#pragma unroll 4
    for (int k = 0; k < E / 4; k++) {
        float4 a = xr[k], w = wr[k];
        s += a.x * w.x + a.y * w.y + a.z * w.z + a.w * w.w;
    }
    g_gconst[j] = s + bih0[j] + bhh0[j];
}

__global__ void k_bias(const float* __restrict__ bih1, const float* __restrict__ bhh1,
                       const float* __restrict__ ebih, const float* __restrict__ ebhh) {
    int i = blockIdx.x * blockDim.x + threadIdx.x;
    if (i < 4096) g_bsum1[i] = bih1[i] + bhh1[i];
    if (i < 8192) g_encb[i] = ebih[i] + ebhh[i];
}

// ---------------- persistent decoder ----------------
// 128 blocks x 256 threads; block owns units [blk*8, blk*8+8) x 4 gates, both layers.
__global__ void __launch_bounds__(256) k_dec(const float* __restrict__ Whh0,
                                             const float* __restrict__ Wih1,
                                             const float* __restrict__ Whh1,
                                             const float* __restrict__ enc_h,
                                             const float* __restrict__ enc_c) {
    extern __shared__ __half sm[];
    __half* A0 = sm;                          // 32 x 1032
    __half* A1 = sm + 33024;
    __half* A2 = sm + 66048;
    float* gsm = (float*)(sm + 99072);        // 32 x 33
    const int tid = threadIdx.x, lane = tid & 31, w = tid >> 5;
    const int u0 = blockIdx.x * 8;

    // weights -> smem (fp32->fp16), rows packed s = gate*8 + ulocal
    for (int i = tid; i < 8192; i += 256) {
        int s = i >> 8;
        int col = (i & 255) * 4;
        size_t grow = (size_t)((s >> 3) * 1024 + u0 + (s & 7));
        float4 v0 = *(const float4*)(Whh0 + grow * 1024 + col);
        float4 v1 = *(const float4*)(Wih1 + grow * 1024 + col);
        float4 v2 = *(const float4*)(Whh1 + grow * 1024 + col);
        __half* p0 = A0 + (size_t)s * 1032 + col;
        p0[0]=__float2half(v0.x); p0[1]=__float2half(v0.y); p0[2]=__float2half(v0.z); p0[3]=__float2half(v0.w);
        __half* p1 = A1 + (size_t)s * 1032 + col;
        p1[0]=__float2half(v1.x); p1[1]=__float2half(v1.y); p1[2]=__float2half(v1.z); p1[3]=__float2half(v1.w);
        __half* p2 = A2 + (size_t)s * 1032 + col;
        p2[0]=__float2half(v2.x); p2[1]=__float2half(v2.y); p2[2]=__float2half(v2.z); p2[3]=__float2half(v2.w);
    }

    const int u = w, b = lane, uu = u0 + u;
    const int hp = st_hidx(uu, b);
    const int xb = seq_base(uu);
    float c0 = enc_c[b * 1024 + uu];
    float c1 = enc_c[32768 + b * 1024 + uu];
    ((__half*)g_h0F[0])[hp] = __float2half(enc_h[b * 1024 + uu]);
    ((__half*)g_h1F[0])[hp] = __float2half(enc_h[32768 + b * 1024 + uu]);
    const float gci = g_gconst[uu],        gcf = g_gconst[1024 + uu];
    const float gcg = g_gconst[2048 + uu], gco = g_gconst[3072 + uu];
    const float b1i = g_bsum1[uu],         b1f = g_bsum1[1024 + uu];
    const float b1g = g_bsum1[2048 + uu],  b1o = g_bsum1[3072 + uu];
    const int mt = w & 1, ntc = (w >> 1) * 8;

    grid_barrier();

    for (int t = 0; t < T; t++) {
        const int p = t & 1;
        // ---- layer 0 cell: gates = Whh0 @ h0[p] + gconst ----
        float acc[4] = {0.f, 0.f, 0.f, 0.f};
        gemm_fr(A0, 1032, 64, g_h0F[p], 32, mt, ntc, lane, acc);
        frag_st(gsm, mt, ntc, lane, acc);
        __syncthreads();
        {
            float iv = gsm[u * 33 + b] + gci;
            float fv = gsm[(8 + u) * 33 + b] + gcf;
            float gv = gsm[(16 + u) * 33 + b] + gcg;
            float ov = gsm[(24 + u) * 33 + b] + gco;
            c0 = sigf(fv) * c0 + sigf(iv) * tanhf(gv);
            float h = sigf(ov) * tanhf(c0);
            ((__half*)g_h0F[1 - p])[hp] = __float2half(h);
        }
        grid_barrier();
        // ---- layer 1 cell: gates = Wih1 @ h0new + Whh1 @ h1[p] + bsum1 ----
        acc[0] = acc[1] = acc[2] = acc[3] = 0.f;
        gemm_fr(A1, 1032, 64, g_h0F[1 - p], 32, mt, ntc, lane, acc);
        gemm_fr(A2, 1032, 64, g_h1F[p],     32, mt, ntc, lane, acc);
        frag_st(gsm, mt, ntc, lane, acc);
        __syncthreads();
        {
            float iv = gsm[u * 33 + b] + b1i;
            float fv = gsm[(8 + u) * 33 + b] + b1f;
            float gv = gsm[(16 + u) * 33 + b] + b1g;
            float ov = gsm[(24 + u) * 33 + b] + b1o;
            c1 = sigf(fv) * c1 + sigf(iv) * tanhf(gv);
            float h = sigf(ov) * tanhf(c1);
            __half hh = __float2half(h);
            ((__half*)g_h1F[1 - p])[hp] = hh;
            ((__half*)g_X2F)[xb + (t * 32 + b) * 4] = hh;
        }
        grid_barrier();
    }
}

// ---------------- encoder input-projection GEMM: Z = X @ Wih^T + bias ----------------
// grid (32 j-blocks of 64 rows, 32 n-blocks of 256, 2 dirs), W tile in smem.
__global__ void __launch_bounds__(256) k_z(int l, const float* __restrict__ eWih) {
    extern __shared__ __half sm[];
    __half* As = sm;   // 64 x 1032
    const int tid = threadIdx.x, lane = tid & 31, w = tid >> 5;
    const int jb = blockIdx.x * 64;
    const int n0 = blockIdx.y * 256;
    const int d = blockIdx.z;
    for (int i = tid; i < 16384; i += 256) {
        int s = i >> 8;
        int col = (i & 255) * 4;
        size_t grow = (size_t)(l * 2 + d) * 2048 + jb + s;
        float4 v = *(const float4*)(eWih + grow * 1024 + col);
        __half* pp = As + (size_t)s * 1032 + col;
        pp[0]=__float2half(v.x); pp[1]=__float2half(v.y); pp[2]=__float2half(v.z); pp[3]=__float2half(v.w);
    }
    __syncthreads();
    const uint2* Bf = l ? g_Y0F : g_X2F;
    const int mt = w & 3;
    const int nh = (w >> 2) * 8;
    const int g = lane >> 2, q = lane & 3;
    float* Zp = g_Z + (size_t)d * 2048 * NSEQ;
    const float bias0 = g_encb[(l * 2 + d) * 2048 + jb + mt * 16 + g];
    const float bias1 = g_encb[(l * 2 + d) * 2048 + jb + mt * 16 + 8 + g];
    const int j0 = jb + mt * 16 + g;
    for (int ch = 0; ch < 16; ch++) {
        float acc[4] = {0.f, 0.f, 0.f, 0.f};
        gemm_fr(As, 1032, 64, Bf, 8192, mt, n0 + ch * 16 + nh, lane, acc);
        int n = n0 + ch * 16 + nh + 2 * q;
        Zp[(size_t)j0 * NSEQ + n]           = acc[0] + bias0;
        Zp[(size_t)j0 * NSEQ + n + 1]       = acc[1] + bias0;
        Zp[(size_t)(j0 + 8) * NSEQ + n]     = acc[2] + bias1;
        Zp[(size_t)(j0 + 8) * NSEQ + n + 1] = acc[3] + bias1;
    }
}

// ---------------- persistent encoder (both directions in one grid) ----------------
// 128 blocks: dir = blk>>6, block owns units [(blk&63)*8, +8) x 4 gates.
__global__ void __launch_bounds__(256) k_enc(int l, const float* __restrict__ eWhh,
                                             float* __restrict__ out) {
    extern __shared__ __half sm[];
    __half* As = sm;                      // 32 x 520
    float* gsm = (float*)(sm + 16640);    // 32 x 33
    const int tid = threadIdx.x, lane = tid & 31, w = tid >> 5;
    const int d = blockIdx.x >> 6;
    const int u0 = (blockIdx.x & 63) * 8;

    for (int i = tid; i < 4096; i += 256) {
        int s = i >> 7;
        int col = (i & 127) * 4;
        size_t grow = (size_t)(l * 2 + d) * 2048 + (s >> 3) * 512 + u0 + (s & 7);
        float4 v = *(const float4*)(eWhh + grow * 512 + col);
        __half* pp = As + (size_t)s * 520 + col;
        pp[0]=__float2half(v.x); pp[1]=__float2half(v.y); pp[2]=__float2half(v.z); pp[3]=__float2half(v.w);
    }

    const int u = w, b = lane, uu = u0 + u;
    const int hp = st_hidx(uu, b);
    const int f = d * 512 + uu;
    const int xb = seq_base(f);
    const int mt = w & 1, ntc = (w >> 1) * 8;
    float c = 0.f;
    const float* Zp = g_Z + (size_t)d * 2048 * NSEQ;
    const float* zi = Zp + (size_t)uu * NSEQ;
    const float* zf = Zp + (size_t)(512 + uu) * NSEQ;
    const float* zg = Zp + (size_t)(1024 + uu) * NSEQ;
    const float* zo = Zp + (size_t)(1536 + uu) * NSEQ;
    __syncthreads();

    for (int s = 0; s < T; s++) {
        const int p = s & 1;
        const int tau = d ? (T - 1 - s) : s;
        float acc[4] = {0.f, 0.f, 0.f, 0.f};
        if (s) gemm_fr(As, 520, 32, g_ehF[d][p], 32, mt, ntc, lane, acc);
        frag_st(gsm, mt, ntc, lane, acc);
        __syncthreads();
        const int n = tau * 32 + b;
        float iv = gsm[u * 33 + b] + zi[n];
        float fv = gsm[(8 + u) * 33 + b] + zf[n];
        float gv = gsm[(16 + u) * 33 + b] + zg[n];
        float ov = gsm[(24 + u) * 33 + b] + zo[n];
        c = sigf(fv) * c + sigf(iv) * tanhf(gv);
        float h = sigf(ov) * tanhf(c);
        __half hh = __float2half(h);
        ((__half*)g_ehF[d][1 - p])[hp] = hh;
        if (l == 0) {
            ((__half*)g_Y0F)[xb + n * 4] = hh;
        } else {
            out[(size_t)b * (T * HD) + (size_t)tau * HD + f] = h;
            if (s == T - 1) {
                out[OUT_OFF_H + b * HD + f] = h;
                out[OUT_OFF_H + 32768 + b * HD + f] = h;
                out[OUT_OFF_C + b * HD + f] = c;
                out[OUT_OFF_C + 32768 + b * HD + f] = c;
            }
        }
        grid_barrier();
    }
}

// ---------------- host launcher ----------------
extern "C" void kernel_launch(void* const* d_in, const int* in_sizes, int n_in,
                              void* d_out, int out_size) {
    (void)in_sizes; (void)n_in; (void)out_size;
    const float* enc_h = (const float*)d_in[1];
    const float* enc_c = (const float*)d_in[2];
    const float* emb   = (const float*)d_in[4];
    const float* Wih0  = (const float*)d_in[5];
    const float* Whh0  = (const float*)d_in[6];
    const float* bih0  = (const float*)d_in[7];
    const float* bhh0  = (const float*)d_in[8];
    const float* Wih1  = (const float*)d_in[9];
    const float* Whh1  = (const float*)d_in[10];
    const float* bih1  = (const float*)d_in[11];
    const float* bhh1  = (const float*)d_in[12];
    const float* eWih  = (const float*)d_in[13];
    const float* eWhh  = (const float*)d_in[14];
    const float* ebih  = (const float*)d_in[15];
    const float* ebhh  = (const float*)d_in[16];
    float* out = (float*)d_out;

    cudaFuncSetAttribute(k_dec, cudaFuncAttributeMaxDynamicSharedMemorySize, 202368);
    cudaFuncSetAttribute(k_z,   cudaFuncAttributeMaxDynamicSharedMemorySize, 132096);
    cudaFuncSetAttribute(k_enc, cudaFuncAttributeMaxDynamicSharedMemorySize, 37504);

    k_gconst<<<16, 256>>>(emb, Wih0, bih0, bhh0);
    k_bias<<<32, 256>>>(bih1, bhh1, ebih, ebhh);
    k_dec<<<128, 256, 202368>>>(Whh0, Wih1, Whh1, enc_h, enc_c);
    for (int l = 0; l < 2; l++) {
        k_z<<<dim3(32, 32, 2), 256, 132096>>>(l, eWih);
        k_enc<<<128, 256, 37504>>>(l, eWhh, out);
    }
}